// round 9
// baseline (speedup 1.0000x reference)
#include <cuda_runtime.h>
#include <cuda_fp16.h>
#include <math.h>
#include <stdint.h>

#define BZ 4
#define LZ 2048
#define WD 2048
#define NHD 32
#define HDM 64
#define MBSZ 16
#define NMBC 128
#define EPSC 1e-6f
#define ELEMS (BZ*LZ*WD)
#define KP 4096            // split-fp16 A: [hi | lo], 2*2048
#define NROWS_B 4352       // 2048 q + 2048 v + 32 lr + pad to 17*256

// ---------------- scratch (device globals; no allocation) ----------------
__device__ float g_xq[ELEMS];
__device__ float g_xv[ELEMS];
__device__ float g_XQ[ELEMS];
__device__ float g_XK[ELEMS];
__device__ float g_scan[ELEMS];
__device__ float g_lr[BZ*NHD*NMBC*MBSZ];
__device__ float g_lrraw[8192 * 32];
__device__ __half g_A_hf[(size_t)8192 * KP];       // [hi | lo]
__device__ __half g_B_hf[(size_t)NROWS_B * 2048];  // hi only (dedup)

// ---------------- PTX helpers ----------------
__device__ __forceinline__ uint32_t smem_u32(const void* p) {
    uint32_t a;
    asm("{ .reg .u64 t; cvta.to.shared.u64 t, %1; cvt.u32.u64 %0, t; }" : "=r"(a) : "l"(p));
    return a;
}
#define CPA16(d, s) asm volatile("cp.async.cg.shared.global [%0], [%1], 16;" :: "r"(d), "l"(s) : "memory")

__device__ __forceinline__ void ldsm_x4(uint32_t a, uint32_t& r0, uint32_t& r1, uint32_t& r2, uint32_t& r3) {
    asm volatile("ldmatrix.sync.aligned.m8n8.x4.shared.b16 {%0,%1,%2,%3}, [%4];"
                 : "=r"(r0), "=r"(r1), "=r"(r2), "=r"(r3) : "r"(a));
}
__device__ __forceinline__ void mma_f16(float* c, const uint32_t* a, const uint32_t* b) {
    asm volatile("mma.sync.aligned.m16n8k16.row.col.f32.f16.f16.f32 "
                 "{%0,%1,%2,%3}, {%4,%5,%6,%7}, {%8,%9}, {%0,%1,%2,%3};"
                 : "+f"(c[0]), "+f"(c[1]), "+f"(c[2]), "+f"(c[3])
                 : "r"(a[0]), "r"(a[1]), "r"(a[2]), "r"(a[3]), "r"(b[0]), "r"(b[1]));
}

// ---------------- split-fp16 helpers ----------------
__device__ __forceinline__ void splitf16(const float4& v, uint2& hi, uint2& lo) {
    __half2 h01 = __floats2half2_rn(v.x, v.y);
    __half2 h23 = __floats2half2_rn(v.z, v.w);
    float2 f01 = __half22float2(h01), f23 = __half22float2(h23);
    __half2 l01 = __floats2half2_rn(v.x - f01.x, v.y - f01.y);
    __half2 l23 = __floats2half2_rn(v.z - f23.x, v.w - f23.y);
    hi.x = *(uint32_t*)&h01; hi.y = *(uint32_t*)&h23;
    lo.x = *(uint32_t*)&l01; lo.y = *(uint32_t*)&l23;
}

// ---------------- A conversion: fp32 [8192,2048] -> fp16 [8192,4096] = [hi|lo] ----------------
__global__ __launch_bounds__(256) void ttt_cvtA(const float* __restrict__ src)
{
    int t = blockIdx.x * 256 + threadIdx.x;
    float4 v = ((const float4*)src)[t];
    int r = t >> 9, c4 = t & 511;
    size_t base = (size_t)r * KP + (c4 << 2);
    uint2 hi, lo;
    splitf16(v, hi, lo);
    *(uint2*)(g_A_hf + base)        = hi;
    *(uint2*)(g_A_hf + base + 2048) = lo;
}

// ---------------- B conversion (3 sources + zero pad): hi plane only ----------------
__global__ __launch_bounds__(256) void ttt_cvtB(const float* __restrict__ w0,
                                                const float* __restrict__ w1,
                                                const float* __restrict__ w2,
                                                int nrows)
{
    int row = blockIdx.x;
    if (row >= nrows) return;
    int tid = threadIdx.x;
    const float* srcp = nullptr;
    if (row < 2048) srcp = w0 + (size_t)row * 2048;
    else if (row < 4096) srcp = w1 + (size_t)(row - 2048) * 2048;
    else if (row < 4128) srcp = w2 + (size_t)(row - 4096) * 2048;
    float4 v0 = make_float4(0, 0, 0, 0), v1 = v0;
    if (srcp) { v0 = ((const float4*)srcp)[tid]; v1 = ((const float4*)srcp)[tid + 256]; }
    uint2 hi, lo;
    splitf16(v0, hi, lo);
    *(uint2*)(g_B_hf + (size_t)row * 2048 + (tid << 2)) = hi;
    splitf16(v1, hi, lo);
    *(uint2*)(g_B_hf + (size_t)row * 2048 + ((tid + 256) << 2)) = hi;
}

// ---------------- fp16 mma.sync GEMM: CTA 128x256, 512 thr, B-dedup, 3-stage ----------------
// C[m,n] = sum_k (A_hi[m,k]+A_lo[m,k]) * B_hi[n,k], K=2048, 32 K-steps of 64.
// Stage: A_hi 16KB | A_lo 16KB | B 32KB = 64KB; 3 stages = 192KB.
#define GS_STAGE 65536
#define GKSTEPS 32
__global__ __launch_bounds__(512) void ttt_hgemm(float* Cext, int fused)
{
    extern __shared__ char smem[];
    uint32_t sb = smem_u32(smem);
    const int tid = threadIdx.x;
    const int wid = tid >> 5, lane = tid & 31;
    const int m0 = blockIdx.y << 7;
    const int n0 = blockIdx.x << 8;
    const int mw = (wid >> 2) << 5;   // 0,32,64,96
    const int nw = (wid & 3) << 6;    // 0,64,128,192

    const __half* Ab = g_A_hf + (size_t)m0 * KP;
    const __half* Bb = g_B_hf + (size_t)n0 * 2048;

    float acc[2][8][4];
#pragma unroll
    for (int i = 0; i < 2; i++)
#pragma unroll
        for (int j = 0; j < 8; j++)
#pragma unroll
            for (int q = 0; q < 4; q++) acc[i][j][q] = 0.0f;

    auto load_stage = [&](int s, int kt) {
        uint32_t sAh = sb + s * GS_STAGE;
        uint32_t sAl = sAh + 16384;
        uint32_t sB  = sAh + 32768;
#pragma unroll
        for (int i = 0; i < 2; i++) {
            int idx = tid + (i << 9);              // 0..1023 -> A rows
            int row = idx >> 3, c = idx & 7;
            uint32_t soff = (uint32_t)(row << 7) + (((uint32_t)(c ^ (row & 7))) << 4);
            const __half* ar = Ab + (size_t)row * KP + kt * 64 + c * 8;
            CPA16(sAh + soff, (const char*)ar);
            CPA16(sAl + soff, (const char*)(ar + 2048));
        }
#pragma unroll
        for (int i = 0; i < 4; i++) {
            int idx = tid + (i << 9);              // 0..2047 -> B rows
            int row = idx >> 3, c = idx & 7;
            uint32_t soff = (uint32_t)(row << 7) + (((uint32_t)(c ^ (row & 7))) << 4);
            CPA16(sB + soff, (const char*)(Bb + (size_t)row * 2048 + kt * 64 + c * 8));
        }
        asm volatile("cp.async.commit_group;" ::: "memory");
    };

    load_stage(0, 0);
    load_stage(1, 1);
    const int lr15 = lane & 15, lhi = lane >> 4;

    for (int kt = 0; kt < GKSTEPS; kt++) {
        int s = kt % 3;
        if (kt < GKSTEPS - 2) {
            asm volatile("cp.async.wait_group 1;" ::: "memory");
        } else {
            asm volatile("cp.async.wait_group 0;" ::: "memory");
        }
        __syncthreads();
        if (kt + 2 < GKSTEPS) load_stage((kt + 2) % 3, kt + 2);

        uint32_t aH = sb + s * GS_STAGE;
        uint32_t aL = aH + 16384;
        uint32_t bB = aH + 32768;
#pragma unroll
        for (int ks = 0; ks < 4; ks++) {
            uint32_t af_h[2][4], af_l[2][4];
#pragma unroll
            for (int mt = 0; mt < 2; mt++) {
                int row = mw + mt * 16 + lr15;
                uint32_t off = (uint32_t)(row << 7) + ((uint32_t)((2 * ks + lhi) ^ (row & 7)) << 4);
                ldsm_x4(aH + off, af_h[mt][0], af_h[mt][1], af_h[mt][2], af_h[mt][3]);
                ldsm_x4(aL + off, af_l[mt][0], af_l[mt][1], af_l[mt][2], af_l[mt][3]);
            }
            uint32_t bf[8][2];
#pragma unroll
            for (int np = 0; np < 4; np++) {
                int row = nw + np * 16 + lr15;
                uint32_t bd = bB + (uint32_t)(row << 7) + ((uint32_t)((2 * ks + lhi) ^ (row & 7)) << 4);
                uint32_t r0, r1, r2, r3;
                ldsm_x4(bd, r0, r1, r2, r3);
                bf[np * 2][0] = r0;     bf[np * 2][1] = r2;
                bf[np * 2 + 1][0] = r1; bf[np * 2 + 1][1] = r3;
            }
#pragma unroll
            for (int mt = 0; mt < 2; mt++)
#pragma unroll
                for (int nt = 0; nt < 8; nt++) {
                    mma_f16(acc[mt][nt], af_h[mt], bf[nt]);
                    mma_f16(acc[mt][nt], af_l[mt], bf[nt]);
                }
        }
        __syncthreads();
    }

    // epilogue
#pragma unroll
    for (int mt = 0; mt < 2; mt++) {
#pragma unroll
        for (int nt = 0; nt < 8; nt++) {
            int col = n0 + nw + nt * 8 + (lane & 3) * 2;
            int row = m0 + mw + mt * 16 + (lane >> 2);
            float2 va = make_float2(acc[mt][nt][0], acc[mt][nt][1]);
            float2 vb = make_float2(acc[mt][nt][2], acc[mt][nt][3]);
            if (!fused) {
                *(float2*)(Cext + (size_t)row * 2048 + col) = va;
                *(float2*)(Cext + (size_t)(row + 8) * 2048 + col) = vb;
            } else if (col < 2048) {
                *(float2*)(g_xq + (size_t)row * 2048 + col) = va;
                *(float2*)(g_xq + (size_t)(row + 8) * 2048 + col) = vb;
            } else if (col < 4096) {
                *(float2*)(g_xv + (size_t)row * 2048 + col - 2048) = va;
                *(float2*)(g_xv + (size_t)(row + 8) * 2048 + col - 2048) = vb;
            } else if (col < 4128) {
                *(float2*)(g_lrraw + (size_t)row * 32 + col - 4096) = va;
                *(float2*)(g_lrraw + (size_t)(row + 8) * 32 + col - 4096) = vb;
            }
        }
    }
}

// ---------------- lr sigmoid + relayout ----------------
__global__ __launch_bounds__(256) void ttt_lr_sig(const float* __restrict__ lrb)
{
    int idx = blockIdx.x * 256 + threadIdx.x;
    int bl = idx >> 5, h = idx & 31;
    float v = g_lrraw[idx];
    float sg = 1.0f / (1.0f + expf(-(v + lrb[h])));
    int b = bl >> 11, l = bl & (LZ - 1);
    g_lr[(((size_t)b * NHD + h) * NMBC + (l >> 4)) * MBSZ + (l & 15)] = sg * (1.0f / 64.0f);
}

// ---------------- causal dwconv + RoPE (vectorized weights, uniform l) ----------------
__global__ __launch_bounds__(256) void ttt_conv_rope(
    const float* __restrict__ cqw, const float* __restrict__ cqb,
    const float* __restrict__ ckw, const float* __restrict__ ckb)
{
    __shared__ float scs[32], ssn[32];
    int idx = blockIdx.x * 256 + threadIdx.x;
    int pr = idx & (WD / 2 - 1);
    int bl = idx >> 10;
    int l  = bl & (LZ - 1);
    int ch = pr * 2;

    if (threadIdx.x < 32) {
        float fr = (float)(l & 15) * exp2f(-(float)threadIdx.x * (13.2877123795f / 32.0f));
        sincosf(fr, &ssn[threadIdx.x], &scs[threadIdx.x]);
    }
    __syncthreads();

    float4 wq0 = ((const float4*)cqw)[ch];
    float4 wq1 = ((const float4*)cqw)[ch + 1];
    float4 wk0 = ((const float4*)ckw)[ch];
    float4 wk1 = ((const float4*)ckw)[ch + 1];
    float2 bq = ((const float2*)cqb)[pr];
    float2 bk = ((const float2*)ckb)[pr];

    const float2* xin = (const float2*)g_xq;
    float q0 = bq.x, q1 = bq.y, k0 = bk.x, k1 = bk.y;
    if (l >= 3) {
        float2 v0 = xin[(size_t)(bl - 3) * (WD / 2) + pr];
        float2 v1 = xin[(size_t)(bl - 2) * (WD / 2) + pr];
        float2 v2 = xin[(size_t)(bl - 1) * (WD / 2) + pr];
        float2 v3 = xin[(size_t)bl * (WD / 2) + pr];
        q0 += v0.x * wq0.x + v1.x * wq0.y + v2.x * wq0.z + v3.x * wq0.w;
        q1 += v0.y * wq1.x + v1.y * wq1.y + v2.y * wq1.z + v3.y * wq1.w;
        k0 += v0.x * wk0.x + v1.x * wk0.y + v2.x * wk0.z + v3.x * wk0.w;
        k1 += v0.y * wk1.x + v1.y * wk1.y + v2.y * wk1.z + v3.y * wk1.w;
    } else {
        const float* wq0a = (const float*)&wq0;
        const float* wq1a = (const float*)&wq1;
        const float* wk0a = (const float*)&wk0;
        const float* wk1a = (const float*)&wk1;
#pragma unroll
        for (int k = 0; k < 4; k++) {
            if (l - 3 + k >= 0) {
                float2 v = xin[(size_t)(bl - 3 + k) * (WD / 2) + pr];
                q0 += v.x * wq0a[k];  q1 += v.y * wq1a[k];
                k0 += v.x * wk0a[k];  k1 += v.y * wk1a[k];
            }
        }
    }
    int i = (ch & 63) >> 1;
    float sn = ssn[i], cs = scs[i];
    ((float2*)g_XQ)[idx] = make_float2(q0 * cs - q1 * sn, q1 * cs + q0 * sn);
    ((float2*)g_XK)[idx] = make_float2(k0 * cs - k1 * sn, k1 * cs + k0 * sn);
}

// ---------------- the TTT scan: one block (256 threads) per (b,h) ----------------
__global__ __launch_bounds__(256) void ttt_scan_kernel(
    const float* __restrict__ lt_idx,
    const float* __restrict__ lnw_g, const float* __restrict__ lnb_g,
    const float* __restrict__ W1g,   const float* __restrict__ b1g)
{
    __shared__ float W1[64][64];
    __shared__ float sxq[16][68], sxk[16][68], sxv[16][68];
    __shared__ float grad[16][68], z[16][68];
    __shared__ float attn[16][16];
    __shared__ float b1[64], lnw[64], lnb[64], lr[16], tok[16];

    int tid = threadIdx.x;
    int b = blockIdx.x >> 5, h = blockIdx.x & 31;

    for (int o = tid; o < 4096; o += 256)
        ((float*)W1)[o] = W1g[(size_t)h * 4096 + o];
    if (tid < 64) {
        b1[tid]  = b1g[h * 64 + tid];
        lnw[tid] = lnw_g[h * 64 + tid];
        lnb[tid] = lnb_g[h * 64 + tid];
    }
    if (tid < 16) tok[tid] = fmaxf(1.0f / (float)(tid + 1) + lt_idx[tid], 0.0f);
    __syncthreads();

    const int warp = tid >> 5, lane = tid & 31;
    const int ii = tid >> 4;
    const int d0 = (tid & 15) * 4;
    const size_t base = ((size_t)b * LZ) * WD + (size_t)h * HDM;

    for (int n = 0; n < NMBC; n++) {
        {
            size_t g0 = base + (size_t)(n * MBSZ + ii) * WD + d0;
            *(float4*)&sxq[ii][d0] = *(const float4*)&g_XQ[g0];
            *(float4*)&sxk[ii][d0] = *(const float4*)&g_XK[g0];
            *(float4*)&sxv[ii][d0] = *(const float4*)&g_xv[g0];
        }
        if (tid < 16) lr[tid] = g_lr[(((size_t)b * NHD + h) * NMBC + n) * MBSZ + tid];
        __syncthreads();

        {
            float4 acc = *(const float4*)&b1[d0];
#pragma unroll 8
            for (int e = 0; e < 64; e++) {
                float xe = sxk[ii][e];
                float4 w = *(const float4*)&W1[e][d0];
                acc.x += xe * w.x; acc.y += xe * w.y; acc.z += xe * w.z; acc.w += xe * w.w;
            }
            *(float4*)&z[ii][d0] = acc;
        }
        {
            int i = tid >> 4, j = tid & 15;
            float s = 0.0f;
#pragma unroll 8
            for (int d = 0; d < 64; d++) s += sxq[i][d] * sxk[j][d];
            attn[i][j] = s;
        }
        __syncthreads();

        {
#pragma unroll
            for (int rr = 0; rr < 2; rr++) {
                int r = warp * 2 + rr;
                float x0 = z[r][lane], x1 = z[r][lane + 32];
                float s = x0 + x1;
#pragma unroll
                for (int o = 16; o; o >>= 1) s += __shfl_xor_sync(0xffffffffu, s, o);
                float mu = s * (1.0f / 64.0f);
                float e0 = x0 - mu, e1 = x1 - mu;
                float v = e0 * e0 + e1 * e1;
#pragma unroll
                for (int o = 16; o; o >>= 1) v += __shfl_xor_sync(0xffffffffu, v, o);
                float rstd = rsqrtf(v * (1.0f / 64.0f) + EPSC);
                float xh0 = e0 * rstd, xh1 = e1 * rstd;
                float t0 = sxv[r][lane] - sxk[r][lane];
                float t1 = sxv[r][lane + 32] - sxk[r][lane + 32];
                float gy0 = (lnw[lane] * xh0 + lnb[lane] - t0) * lnw[lane];
                float gy1 = (lnw[lane + 32] * xh1 + lnb[lane + 32] - t1) * lnw[lane + 32];
                float s1 = gy0 + gy1, s2 = gy0 * xh0 + gy1 * xh1;
#pragma unroll
                for (int o = 16; o; o >>= 1) {
                    s1 += __shfl_xor_sync(0xffffffffu, s1, o);
                    s2 += __shfl_xor_sync(0xffffffffu, s2, o);
                }
                float sc = rstd * (1.0f / 64.0f);
                grad[r][lane]      = (64.0f * gy0 - s1 - xh0 * s2) * sc;
                grad[r][lane + 32] = (64.0f * gy1 - s1 - xh1 * s2) * sc;
            }
        }
        __syncthreads();

        {
            float4 acc = *(const float4*)&b1[d0];
#pragma unroll 8
            for (int e = 0; e < 64; e++) {
                float xe = sxq[ii][e];
                float4 w = *(const float4*)&W1[e][d0];
                acc.x += xe * w.x; acc.y += xe * w.y; acc.z += xe * w.z; acc.w += xe * w.w;
            }
            float tk = tok[ii];
            for (int j = 0; j <= ii; j++) {
                float cf = tk * lr[j] * (attn[ii][j] + 1.0f);
                float4 gr = *(const float4*)&grad[j][d0];
                acc.x -= cf * gr.x; acc.y -= cf * gr.y; acc.z -= cf * gr.z; acc.w -= cf * gr.w;
            }
            *(float4*)&z[ii][d0] = acc;
        }
        __syncthreads();

        {
#pragma unroll
            for (int rr = 0; rr < 2; rr++) {
                int r = warp * 2 + rr;
                float x0 = z[r][lane], x1 = z[r][lane + 32];
                float s = x0 + x1;
#pragma unroll
                for (int o = 16; o; o >>= 1) s += __shfl_xor_sync(0xffffffffu, s, o);
                float mu = s * (1.0f / 64.0f);
                float e0 = x0 - mu, e1 = x1 - mu;
                float v = e0 * e0 + e1 * e1;
#pragma unroll
                for (int o = 16; o; o >>= 1) v += __shfl_xor_sync(0xffffffffu, v, o);
                float rstd = rsqrtf(v * (1.0f / 64.0f) + EPSC);
                size_t go = base + (size_t)(n * MBSZ + r) * WD;
                g_scan[go + lane]      = sxq[r][lane]      + lnw[lane] * (e0 * rstd)      + lnb[lane];
                g_scan[go + lane + 32] = sxq[r][lane + 32] + lnw[lane + 32] * (e1 * rstd) + lnb[lane + 32];
            }
        }

        {
            float te = tok[15];
#pragma unroll
            for (int p = 0; p < 4; p++) {
                int d = ii * 4 + p;
                float4 acc = *(const float4*)&W1[d][d0];
#pragma unroll
                for (int j = 0; j < 16; j++) {
                    float cf = te * lr[j] * sxk[j][d];
                    float4 gr = *(const float4*)&grad[j][d0];
                    acc.x -= cf * gr.x; acc.y -= cf * gr.y; acc.z -= cf * gr.z; acc.w -= cf * gr.w;
                }
                *(float4*)&W1[d][d0] = acc;
            }
            if (tid < 64) {
                float s = 0.0f;
#pragma unroll
                for (int j = 0; j < 16; j++) s += lr[j] * grad[j][tid];
                b1[tid] -= te * s;
            }
        }
        __syncthreads();
    }
}

// ---------------- post layer-norm fused with A split-fp16 conversion ----------------
__global__ __launch_bounds__(256) void ttt_postnorm_cvt(
    const float* __restrict__ pw, const float* __restrict__ pb)
{
    __shared__ float red[8];
    int bl = blockIdx.x, tid = threadIdx.x;
    int lane = tid & 31, warp = tid >> 5;
    const float4* src = (const float4*)(g_scan + (size_t)bl * WD);
    float4 v0 = src[tid], v1 = src[tid + 256];

    float s = v0.x + v0.y + v0.z + v0.w + v1.x + v1.y + v1.z + v1.w;
#pragma unroll
    for (int o = 16; o; o >>= 1) s += __shfl_xor_sync(0xffffffffu, s, o);
    if (lane == 0) red[warp] = s;
    __syncthreads();
    float tot = 0.0f;
#pragma unroll
    for (int i = 0; i < 8; i++) tot += red[i];
    float mu = tot * (1.0f / 2048.0f);
    __syncthreads();

    float q =
        (v0.x - mu) * (v0.x - mu) + (v0.y - mu) * (v0.y - mu) +
        (v0.z - mu) * (v0.z - mu) + (v0.w - mu) * (v0.w - mu) +
        (v1.x - mu) * (v1.x - mu) + (v1.y - mu) * (v1.y - mu) +
        (v1.z - mu) * (v1.z - mu) + (v1.w - mu) * (v1.w - mu);
#pragma unroll
    for (int o = 16; o; o >>= 1) q += __shfl_xor_sync(0xffffffffu, q, o);
    if (lane == 0) red[warp] = q;
    __syncthreads();
    float qt = 0.0f;
#pragma unroll
    for (int i = 0; i < 8; i++) qt += red[i];
    float rstd = rsqrtf(qt * (1.0f / 2048.0f) + EPSC);

    float4 w0 = ((const float4*)pw)[tid], w1 = ((const float4*)pw)[tid + 256];
    float4 b0 = ((const float4*)pb)[tid], b1v = ((const float4*)pb)[tid + 256];
    float4 o0, o1;
    o0.x = (v0.x - mu) * rstd * w0.x + b0.x;
    o0.y = (v0.y - mu) * rstd * w0.y + b0.y;
    o0.z = (v0.z - mu) * rstd * w0.z + b0.z;
    o0.w = (v0.w - mu) * rstd * w0.w + b0.w;
    o1.x = (v1.x - mu) * rstd * w1.x + b1v.x;
    o1.y = (v1.y - mu) * rstd * w1.y + b1v.y;
    o1.z = (v1.z - mu) * rstd * w1.z + b1v.z;
    o1.w = (v1.w - mu) * rstd * w1.w + b1v.w;

    size_t base0 = (size_t)bl * KP + (tid << 2);
    size_t base1 = (size_t)bl * KP + ((tid + 256) << 2);
    uint2 hi, lo;
    splitf16(o0, hi, lo);
    *(uint2*)(g_A_hf + base0)        = hi;
    *(uint2*)(g_A_hf + base0 + 2048) = lo;
    splitf16(o1, hi, lo);
    *(uint2*)(g_A_hf + base1)        = hi;
    *(uint2*)(g_A_hf + base1 + 2048) = lo;
}

// ---------------- launcher ----------------
extern "C" void kernel_launch(void* const* d_in, const int* in_sizes, int n_in,
                              void* d_out, int out_size)
{
    const float* hs  = (const float*)d_in[0];
    const float* q_w = (const float*)d_in[1];
    const float* v_w = (const float*)d_in[2];
    const float* o_w = (const float*)d_in[3];
    const float* cqw = (const float*)d_in[4];
    const float* cqb = (const float*)d_in[5];
    const float* ckw = (const float*)d_in[6];
    const float* ckb = (const float*)d_in[7];
    const float* lrw = (const float*)d_in[8];
    const float* lrb = (const float*)d_in[9];
    const float* lti = (const float*)d_in[10];
    const float* tnw = (const float*)d_in[11];
    const float* tnb = (const float*)d_in[12];
    const float* W1i = (const float*)d_in[13];
    const float* b1i = (const float*)d_in[14];
    const float* pnw = (const float*)d_in[15];
    const float* pnb = (const float*)d_in[16];
    float* out = (float*)d_out;

    static int smem_set = 0;
    if (!smem_set) {
        cudaFuncSetAttribute(ttt_hgemm, cudaFuncAttributeMaxDynamicSharedMemorySize, 3 * GS_STAGE);
        smem_set = 1;
    }

    // fused QV+lr projection: A=hs, B=[q_w; v_w; lr_w; pad]
    ttt_cvtA<<<16384, 256>>>(hs);
    ttt_cvtB<<<NROWS_B, 256>>>(q_w, v_w, lrw, NROWS_B);
    ttt_hgemm<<<dim3(17, 64), 512, 3 * GS_STAGE>>>(nullptr, 1);   // -> g_xq, g_xv, g_lrraw

    ttt_conv_rope<<<(ELEMS / 2) / 256, 256>>>(cqw, cqb, ckw, ckb);
    ttt_lr_sig<<<1024, 256>>>(lrb);
    ttt_scan_kernel<<<BZ * NHD, 256>>>(lti, tnw, tnb, W1i, b1i);

    // B for final GEMM (stream-ordered after GEMM1 read g_B_hf)
    ttt_cvtB<<<2048, 256>>>(o_w, o_w, o_w, 2048);
    ttt_postnorm_cvt<<<BZ * LZ, 256>>>(pnw, pnb);                 // -> g_A_hf

    ttt_hgemm<<<dim3(8, 64), 512, 3 * GS_STAGE>>>(out, 0);
}

// round 10
// speedup vs baseline: 1.0952x; 1.0952x over previous
#include <cuda_runtime.h>
#include <cuda_fp16.h>
#include <math.h>
#include <stdint.h>

#define BZ 4
#define LZ 2048
#define WD 2048
#define NHD 32
#define HDM 64
#define MBSZ 16
#define NMBC 128
#define EPSC 1e-6f
#define ELEMS (BZ*LZ*WD)
#define KP 4096            // split-fp16 A: [hi | lo]
#define NROWS_B 4224       // 2048 q + 2048 v + 32 lr + 96 pad (33*128)

// ---------------- scratch (device globals; no allocation) ----------------
__device__ float g_xq[ELEMS];
__device__ float g_xv[ELEMS];
__device__ float g_XQ[ELEMS];
__device__ float g_XK[ELEMS];
__device__ float g_scan[ELEMS];
__device__ float g_lr[BZ*NHD*NMBC*MBSZ];
__device__ float g_lrraw[8192 * 32];
__device__ __half g_A_hf[(size_t)8192 * KP];       // [hi | lo]
__device__ __half g_B_hf[(size_t)NROWS_B * 2048];  // hi plane only (dedup)

// ---------------- PTX helpers ----------------
__device__ __forceinline__ uint32_t smem_u32(const void* p) {
    uint32_t a;
    asm("{ .reg .u64 t; cvta.to.shared.u64 t, %1; cvt.u32.u64 %0, t; }" : "=r"(a) : "l"(p));
    return a;
}
#define CPA16(d, s) asm volatile("cp.async.cg.shared.global [%0], [%1], 16;" :: "r"(d), "l"(s) : "memory")

__device__ __forceinline__ void ldsm_x4(uint32_t a, uint32_t& r0, uint32_t& r1, uint32_t& r2, uint32_t& r3) {
    asm volatile("ldmatrix.sync.aligned.m8n8.x4.shared.b16 {%0,%1,%2,%3}, [%4];"
                 : "=r"(r0), "=r"(r1), "=r"(r2), "=r"(r3) : "r"(a));
}
__device__ __forceinline__ void mma_f16(float* c, const uint32_t* a, const uint32_t* b) {
    asm volatile("mma.sync.aligned.m16n8k16.row.col.f32.f16.f16.f32 "
                 "{%0,%1,%2,%3}, {%4,%5,%6,%7}, {%8,%9}, {%0,%1,%2,%3};"
                 : "+f"(c[0]), "+f"(c[1]), "+f"(c[2]), "+f"(c[3])
                 : "r"(a[0]), "r"(a[1]), "r"(a[2]), "r"(a[3]), "r"(b[0]), "r"(b[1]));
}

// ---------------- split-fp16 helpers ----------------
__device__ __forceinline__ void splitf16(const float4& v, uint2& hi, uint2& lo) {
    __half2 h01 = __floats2half2_rn(v.x, v.y);
    __half2 h23 = __floats2half2_rn(v.z, v.w);
    float2 f01 = __half22float2(h01), f23 = __half22float2(h23);
    __half2 l01 = __floats2half2_rn(v.x - f01.x, v.y - f01.y);
    __half2 l23 = __floats2half2_rn(v.z - f23.x, v.w - f23.y);
    hi.x = *(uint32_t*)&h01; hi.y = *(uint32_t*)&h23;
    lo.x = *(uint32_t*)&l01; lo.y = *(uint32_t*)&l23;
}

// ---------------- A conversion: fp32 [8192,2048] -> fp16 [8192,4096] = [hi|lo] ----------------
__global__ __launch_bounds__(256) void ttt_cvtA(const float* __restrict__ src)
{
    int t = blockIdx.x * 256 + threadIdx.x;
    float4 v = ((const float4*)src)[t];
    int r = t >> 9, c4 = t & 511;
    size_t base = (size_t)r * KP + (c4 << 2);
    uint2 hi, lo;
    splitf16(v, hi, lo);
    *(uint2*)(g_A_hf + base)        = hi;
    *(uint2*)(g_A_hf + base + 2048) = lo;
}

// ---------------- B conversion (3 sources + zero pad): hi plane only ----------------
__global__ __launch_bounds__(256) void ttt_cvtB(const float* __restrict__ w0,
                                                const float* __restrict__ w1,
                                                const float* __restrict__ w2)
{
    int row = blockIdx.x;
    int tid = threadIdx.x;
    const float* srcp = nullptr;
    if (row < 2048) srcp = w0 + (size_t)row * 2048;
    else if (row < 4096) srcp = w1 + (size_t)(row - 2048) * 2048;
    else if (row < 4128) srcp = w2 + (size_t)(row - 4096) * 2048;
    float4 v0 = make_float4(0, 0, 0, 0), v1 = v0;
    if (srcp) { v0 = ((const float4*)srcp)[tid]; v1 = ((const float4*)srcp)[tid + 256]; }
    uint2 hi, lo;
    splitf16(v0, hi, lo);
    *(uint2*)(g_B_hf + (size_t)row * 2048 + (tid << 2)) = hi;
    splitf16(v1, hi, lo);
    *(uint2*)(g_B_hf + (size_t)row * 2048 + ((tid + 256) << 2)) = hi;
}

// ---------------- fp16 mma.sync GEMM: 128x128, 256 thr, B-dedup, 2-stage x 48KB ----------------
// C[m,n] = sum_k (A_hi[m,k]+A_lo[m,k]) * B_hi[n,k], K=2048, 32 K-steps of 64.
// Stage: A_hi 16KB | A_lo 16KB | B 16KB = 48KB; 2 stages = 96KB -> 2 CTAs/SM.
#define GS_STAGE 49152
#define GKSTEPS 32
__global__ __launch_bounds__(256, 2) void ttt_hgemm(float* Cext, int fused)
{
    extern __shared__ char smem[];
    uint32_t sb = smem_u32(smem);
    const int tid = threadIdx.x;
    const int wid = tid >> 5, lane = tid & 31;
    const int m0 = blockIdx.y << 7;
    const int n0 = blockIdx.x << 7;
    const int mw = (wid >> 2) << 6;       // 0 or 64
    const int nw = (wid & 3) << 5;        // 0,32,64,96

    const __half* Ab = g_A_hf + (size_t)m0 * KP;
    const __half* Bb = g_B_hf + (size_t)n0 * 2048;

    float acc[4][4][4];
#pragma unroll
    for (int i = 0; i < 4; i++)
#pragma unroll
        for (int j = 0; j < 4; j++)
#pragma unroll
            for (int q = 0; q < 4; q++) acc[i][j][q] = 0.0f;

    auto load_stage = [&](int s, int kt) {
        uint32_t sAh = sb + s * GS_STAGE;
        uint32_t sAl = sAh + 16384;
        uint32_t sB  = sAh + 32768;
#pragma unroll
        for (int i = 0; i < 4; i++) {
            int idx = tid + (i << 8);              // 0..1023
            int row = idx >> 3, c = idx & 7;
            uint32_t soff = (uint32_t)(row << 7) + (((uint32_t)(c ^ (row & 7))) << 4);
            const __half* ar = Ab + (size_t)row * KP + kt * 64 + c * 8;
            CPA16(sAh + soff, (const char*)ar);
            CPA16(sAl + soff, (const char*)(ar + 2048));
            CPA16(sB + soff, (const char*)(Bb + (size_t)row * 2048 + kt * 64 + c * 8));
        }
        asm volatile("cp.async.commit_group;" ::: "memory");
    };

    load_stage(0, 0);
    const int lr15 = lane & 15, lhi = lane >> 4;

    for (int kt = 0; kt < GKSTEPS; kt++) {
        int s = kt & 1;
        if (kt + 1 < GKSTEPS) {
            load_stage(s ^ 1, kt + 1);
            asm volatile("cp.async.wait_group 1;" ::: "memory");
        } else {
            asm volatile("cp.async.wait_group 0;" ::: "memory");
        }
        __syncthreads();

        uint32_t aH = sb + s * GS_STAGE;
        uint32_t aL = aH + 16384;
        uint32_t bB = aH + 32768;
#pragma unroll
        for (int ks = 0; ks < 4; ks++) {
            uint32_t bf[4][2];
#pragma unroll
            for (int np = 0; np < 2; np++) {
                int row = nw + np * 16 + lr15;
                uint32_t bd = bB + (uint32_t)(row << 7) + ((uint32_t)((2 * ks + lhi) ^ (row & 7)) << 4);
                uint32_t r0, r1, r2, r3;
                ldsm_x4(bd, r0, r1, r2, r3);
                bf[np * 2][0] = r0;     bf[np * 2][1] = r2;
                bf[np * 2 + 1][0] = r1; bf[np * 2 + 1][1] = r3;
            }
            uint32_t af[4][4];
            // hi plane
#pragma unroll
            for (int mt = 0; mt < 4; mt++) {
                int row = mw + mt * 16 + lr15;
                uint32_t ad = aH + (uint32_t)(row << 7) + ((uint32_t)((2 * ks + lhi) ^ (row & 7)) << 4);
                ldsm_x4(ad, af[mt][0], af[mt][1], af[mt][2], af[mt][3]);
            }
#pragma unroll
            for (int mt = 0; mt < 4; mt++)
#pragma unroll
                for (int nt = 0; nt < 4; nt++)
                    mma_f16(acc[mt][nt], af[mt], bf[nt]);
            // lo plane (reuse af registers)
#pragma unroll
            for (int mt = 0; mt < 4; mt++) {
                int row = mw + mt * 16 + lr15;
                uint32_t ad = aL + (uint32_t)(row << 7) + ((uint32_t)((2 * ks + lhi) ^ (row & 7)) << 4);
                ldsm_x4(ad, af[mt][0], af[mt][1], af[mt][2], af[mt][3]);
            }
#pragma unroll
            for (int mt = 0; mt < 4; mt++)
#pragma unroll
                for (int nt = 0; nt < 4; nt++)
                    mma_f16(acc[mt][nt], af[mt], bf[nt]);
        }
        __syncthreads();
    }

    // epilogue
#pragma unroll
    for (int mt = 0; mt < 4; mt++) {
#pragma unroll
        for (int nt = 0; nt < 4; nt++) {
            int col = n0 + nw + nt * 8 + (lane & 3) * 2;
            int row = m0 + mw + mt * 16 + (lane >> 2);
            float2 va = make_float2(acc[mt][nt][0], acc[mt][nt][1]);
            float2 vb = make_float2(acc[mt][nt][2], acc[mt][nt][3]);
            if (!fused) {
                *(float2*)(Cext + (size_t)row * 2048 + col) = va;
                *(float2*)(Cext + (size_t)(row + 8) * 2048 + col) = vb;
            } else if (col < 2048) {
                *(float2*)(g_xq + (size_t)row * 2048 + col) = va;
                *(float2*)(g_xq + (size_t)(row + 8) * 2048 + col) = vb;
            } else if (col < 4096) {
                *(float2*)(g_xv + (size_t)row * 2048 + col - 2048) = va;
                *(float2*)(g_xv + (size_t)(row + 8) * 2048 + col - 2048) = vb;
            } else if (col < 4128) {
                *(float2*)(g_lrraw + (size_t)row * 32 + col - 4096) = va;
                *(float2*)(g_lrraw + (size_t)(row + 8) * 32 + col - 4096) = vb;
            }
        }
    }
}

// ---------------- lr sigmoid + relayout ----------------
__global__ __launch_bounds__(256) void ttt_lr_sig(const float* __restrict__ lrb)
{
    int idx = blockIdx.x * 256 + threadIdx.x;
    int bl = idx >> 5, h = idx & 31;
    float v = g_lrraw[idx];
    float sg = 1.0f / (1.0f + expf(-(v + lrb[h])));
    int b = bl >> 11, l = bl & (LZ - 1);
    g_lr[(((size_t)b * NHD + h) * NMBC + (l >> 4)) * MBSZ + (l & 15)] = sg * (1.0f / 64.0f);
}

// ---------------- causal dwconv + RoPE (vectorized weights, uniform l) ----------------
__global__ __launch_bounds__(256) void ttt_conv_rope(
    const float* __restrict__ cqw, const float* __restrict__ cqb,
    const float* __restrict__ ckw, const float* __restrict__ ckb)
{
    __shared__ float scs[32], ssn[32];
    int idx = blockIdx.x * 256 + threadIdx.x;
    int pr = idx & (WD / 2 - 1);
    int bl = idx >> 10;
    int l  = bl & (LZ - 1);
    int ch = pr * 2;

    if (threadIdx.x < 32) {
        float fr = (float)(l & 15) * exp2f(-(float)threadIdx.x * (13.2877123795f / 32.0f));
        sincosf(fr, &ssn[threadIdx.x], &scs[threadIdx.x]);
    }
    __syncthreads();

    float4 wq0 = ((const float4*)cqw)[ch];
    float4 wq1 = ((const float4*)cqw)[ch + 1];
    float4 wk0 = ((const float4*)ckw)[ch];
    float4 wk1 = ((const float4*)ckw)[ch + 1];
    float2 bq = ((const float2*)cqb)[pr];
    float2 bk = ((const float2*)ckb)[pr];

    const float2* xin = (const float2*)g_xq;
    float q0 = bq.x, q1 = bq.y, k0 = bk.x, k1 = bk.y;
    if (l >= 3) {
        float2 v0 = xin[(size_t)(bl - 3) * (WD / 2) + pr];
        float2 v1 = xin[(size_t)(bl - 2) * (WD / 2) + pr];
        float2 v2 = xin[(size_t)(bl - 1) * (WD / 2) + pr];
        float2 v3 = xin[(size_t)bl * (WD / 2) + pr];
        q0 += v0.x * wq0.x + v1.x * wq0.y + v2.x * wq0.z + v3.x * wq0.w;
        q1 += v0.y * wq1.x + v1.y * wq1.y + v2.y * wq1.z + v3.y * wq1.w;
        k0 += v0.x * wk0.x + v1.x * wk0.y + v2.x * wk0.z + v3.x * wk0.w;
        k1 += v0.y * wk1.x + v1.y * wk1.y + v2.y * wk1.z + v3.y * wk1.w;
    } else {
        const float* wq0a = (const float*)&wq0;
        const float* wq1a = (const float*)&wq1;
        const float* wk0a = (const float*)&wk0;
        const float* wk1a = (const float*)&wk1;
#pragma unroll
        for (int k = 0; k < 4; k++) {
            if (l - 3 + k >= 0) {
                float2 v = xin[(size_t)(bl - 3 + k) * (WD / 2) + pr];
                q0 += v.x * wq0a[k];  q1 += v.y * wq1a[k];
                k0 += v.x * wk0a[k];  k1 += v.y * wk1a[k];
            }
        }
    }
    int i = (ch & 63) >> 1;
    float sn = ssn[i], cs = scs[i];
    ((float2*)g_XQ)[idx] = make_float2(q0 * cs - q1 * sn, q1 * cs + q0 * sn);
    ((float2*)g_XK)[idx] = make_float2(k0 * cs - k1 * sn, k1 * cs + k0 * sn);
}

// ---------------- the TTT scan: one block (256 threads) per (b,h) ----------------
__global__ __launch_bounds__(256) void ttt_scan_kernel(
    const float* __restrict__ lt_idx,
    const float* __restrict__ lnw_g, const float* __restrict__ lnb_g,
    const float* __restrict__ W1g,   const float* __restrict__ b1g)
{
    __shared__ float W1[64][64];
    __shared__ float sxq[16][68], sxk[16][68], sxv[16][68];
    __shared__ float grad[16][68], z[16][68];
    __shared__ float attn[16][16];
    __shared__ float b1[64], lnw[64], lnb[64], lr[16], tok[16];

    int tid = threadIdx.x;
    int b = blockIdx.x >> 5, h = blockIdx.x & 31;

    for (int o = tid; o < 4096; o += 256)
        ((float*)W1)[o] = W1g[(size_t)h * 4096 + o];
    if (tid < 64) {
        b1[tid]  = b1g[h * 64 + tid];
        lnw[tid] = lnw_g[h * 64 + tid];
        lnb[tid] = lnb_g[h * 64 + tid];
    }
    if (tid < 16) tok[tid] = fmaxf(1.0f / (float)(tid + 1) + lt_idx[tid], 0.0f);
    __syncthreads();

    const int warp = tid >> 5, lane = tid & 31;
    const int ii = tid >> 4;
    const int d0 = (tid & 15) * 4;
    const size_t base = ((size_t)b * LZ) * WD + (size_t)h * HDM;

    for (int n = 0; n < NMBC; n++) {
        {
            size_t g0 = base + (size_t)(n * MBSZ + ii) * WD + d0;
            *(float4*)&sxq[ii][d0] = *(const float4*)&g_XQ[g0];
            *(float4*)&sxk[ii][d0] = *(const float4*)&g_XK[g0];
            *(float4*)&sxv[ii][d0] = *(const float4*)&g_xv[g0];
        }
        if (tid < 16) lr[tid] = g_lr[(((size_t)b * NHD + h) * NMBC + n) * MBSZ + tid];
        __syncthreads();

        {
            float4 acc = *(const float4*)&b1[d0];
#pragma unroll 8
            for (int e = 0; e < 64; e++) {
                float xe = sxk[ii][e];
                float4 w = *(const float4*)&W1[e][d0];
                acc.x += xe * w.x; acc.y += xe * w.y; acc.z += xe * w.z; acc.w += xe * w.w;
            }
            *(float4*)&z[ii][d0] = acc;
        }
        {
            int i = tid >> 4, j = tid & 15;
            float s = 0.0f;
#pragma unroll 8
            for (int d = 0; d < 64; d++) s += sxq[i][d] * sxk[j][d];
            attn[i][j] = s;
        }
        __syncthreads();

        {
#pragma unroll
            for (int rr = 0; rr < 2; rr++) {
                int r = warp * 2 + rr;
                float x0 = z[r][lane], x1 = z[r][lane + 32];
                float s = x0 + x1;
#pragma unroll
                for (int o = 16; o; o >>= 1) s += __shfl_xor_sync(0xffffffffu, s, o);
                float mu = s * (1.0f / 64.0f);
                float e0 = x0 - mu, e1 = x1 - mu;
                float v = e0 * e0 + e1 * e1;
#pragma unroll
                for (int o = 16; o; o >>= 1) v += __shfl_xor_sync(0xffffffffu, v, o);
                float rstd = rsqrtf(v * (1.0f / 64.0f) + EPSC);
                float xh0 = e0 * rstd, xh1 = e1 * rstd;
                float t0 = sxv[r][lane] - sxk[r][lane];
                float t1 = sxv[r][lane + 32] - sxk[r][lane + 32];
                float gy0 = (lnw[lane] * xh0 + lnb[lane] - t0) * lnw[lane];
                float gy1 = (lnw[lane + 32] * xh1 + lnb[lane + 32] - t1) * lnw[lane + 32];
                float s1 = gy0 + gy1, s2 = gy0 * xh0 + gy1 * xh1;
#pragma unroll
                for (int o = 16; o; o >>= 1) {
                    s1 += __shfl_xor_sync(0xffffffffu, s1, o);
                    s2 += __shfl_xor_sync(0xffffffffu, s2, o);
                }
                float sc = rstd * (1.0f / 64.0f);
                grad[r][lane]      = (64.0f * gy0 - s1 - xh0 * s2) * sc;
                grad[r][lane + 32] = (64.0f * gy1 - s1 - xh1 * s2) * sc;
            }
        }
        __syncthreads();

        {
            float4 acc = *(const float4*)&b1[d0];
#pragma unroll 8
            for (int e = 0; e < 64; e++) {
                float xe = sxq[ii][e];
                float4 w = *(const float4*)&W1[e][d0];
                acc.x += xe * w.x; acc.y += xe * w.y; acc.z += xe * w.z; acc.w += xe * w.w;
            }
            float tk = tok[ii];
            for (int j = 0; j <= ii; j++) {
                float cf = tk * lr[j] * (attn[ii][j] + 1.0f);
                float4 gr = *(const float4*)&grad[j][d0];
                acc.x -= cf * gr.x; acc.y -= cf * gr.y; acc.z -= cf * gr.z; acc.w -= cf * gr.w;
            }
            *(float4*)&z[ii][d0] = acc;
        }
        __syncthreads();

        {
#pragma unroll
            for (int rr = 0; rr < 2; rr++) {
                int r = warp * 2 + rr;
                float x0 = z[r][lane], x1 = z[r][lane + 32];
                float s = x0 + x1;
#pragma unroll
                for (int o = 16; o; o >>= 1) s += __shfl_xor_sync(0xffffffffu, s, o);
                float mu = s * (1.0f / 64.0f);
                float e0 = x0 - mu, e1 = x1 - mu;
                float v = e0 * e0 + e1 * e1;
#pragma unroll
                for (int o = 16; o; o >>= 1) v += __shfl_xor_sync(0xffffffffu, v, o);
                float rstd = rsqrtf(v * (1.0f / 64.0f) + EPSC);
                size_t go = base + (size_t)(n * MBSZ + r) * WD;
                g_scan[go + lane]      = sxq[r][lane]      + lnw[lane] * (e0 * rstd)      + lnb[lane];
                g_scan[go + lane + 32] = sxq[r][lane + 32] + lnw[lane + 32] * (e1 * rstd) + lnb[lane + 32];
            }
        }

        {
            float te = tok[15];
#pragma unroll
            for (int p = 0; p < 4; p++) {
                int d = ii * 4 + p;
                float4 acc = *(const float4*)&W1[d][d0];
#pragma unroll
                for (int j = 0; j < 16; j++) {
                    float cf = te * lr[j] * sxk[j][d];
                    float4 gr = *(const float4*)&grad[j][d0];
                    acc.x -= cf * gr.x; acc.y -= cf * gr.y; acc.z -= cf * gr.z; acc.w -= cf * gr.w;
                }
                *(float4*)&W1[d][d0] = acc;
            }
            if (tid < 64) {
                float s = 0.0f;
#pragma unroll
                for (int j = 0; j < 16; j++) s += lr[j] * grad[j][tid];
                b1[tid] -= te * s;
            }
        }
        __syncthreads();
    }
}

// ---------------- post layer-norm fused with A split-fp16 conversion ----------------
__global__ __launch_bounds__(256) void ttt_postnorm_cvt(
    const float* __restrict__ pw, const float* __restrict__ pb)
{
    __shared__ float red[8];
    int bl = blockIdx.x, tid = threadIdx.x;
    int lane = tid & 31, warp = tid >> 5;
    const float4* src = (const float4*)(g_scan + (size_t)bl * WD);
    float4 v0 = src[tid], v1 = src[tid + 256];

    float s = v0.x + v0.y + v0.z + v0.w + v1.x + v1.y + v1.z + v1.w;
#pragma unroll
    for (int o = 16; o; o >>= 1) s += __shfl_xor_sync(0xffffffffu, s, o);
    if (lane == 0) red[warp] = s;
    __syncthreads();
    float tot = 0.0f;
#pragma unroll
    for (int i = 0; i < 8; i++) tot += red[i];
    float mu = tot * (1.0f / 2048.0f);
    __syncthreads();

    float q =
        (v0.x - mu) * (v0.x - mu) + (v0.y - mu) * (v0.y - mu) +
        (v0.z - mu) * (v0.z - mu) + (v0.w - mu) * (v0.w - mu) +
        (v1.x - mu) * (v1.x - mu) + (v1.y - mu) * (v1.y - mu) +
        (v1.z - mu) * (v1.z - mu) + (v1.w - mu) * (v1.w - mu);
#pragma unroll
    for (int o = 16; o; o >>= 1) q += __shfl_xor_sync(0xffffffffu, q, o);
    if (lane == 0) red[warp] = q;
    __syncthreads();
    float qt = 0.0f;
#pragma unroll
    for (int i = 0; i < 8; i++) qt += red[i];
    float rstd = rsqrtf(qt * (1.0f / 2048.0f) + EPSC);

    float4 w0 = ((const float4*)pw)[tid], w1 = ((const float4*)pw)[tid + 256];
    float4 b0 = ((const float4*)pb)[tid], b1v = ((const float4*)pb)[tid + 256];
    float4 o0, o1;
    o0.x = (v0.x - mu) * rstd * w0.x + b0.x;
    o0.y = (v0.y - mu) * rstd * w0.y + b0.y;
    o0.z = (v0.z - mu) * rstd * w0.z + b0.z;
    o0.w = (v0.w - mu) * rstd * w0.w + b0.w;
    o1.x = (v1.x - mu) * rstd * w1.x + b1v.x;
    o1.y = (v1.y - mu) * rstd * w1.y + b1v.y;
    o1.z = (v1.z - mu) * rstd * w1.z + b1v.z;
    o1.w = (v1.w - mu) * rstd * w1.w + b1v.w;

    size_t base0 = (size_t)bl * KP + (tid << 2);
    size_t base1 = (size_t)bl * KP + ((tid + 256) << 2);
    uint2 hi, lo;
    splitf16(o0, hi, lo);
    *(uint2*)(g_A_hf + base0)        = hi;
    *(uint2*)(g_A_hf + base0 + 2048) = lo;
    splitf16(o1, hi, lo);
    *(uint2*)(g_A_hf + base1)        = hi;
    *(uint2*)(g_A_hf + base1 + 2048) = lo;
}

// ---------------- launcher ----------------
extern "C" void kernel_launch(void* const* d_in, const int* in_sizes, int n_in,
                              void* d_out, int out_size)
{
    const float* hs  = (const float*)d_in[0];
    const float* q_w = (const float*)d_in[1];
    const float* v_w = (const float*)d_in[2];
    const float* o_w = (const float*)d_in[3];
    const float* cqw = (const float*)d_in[4];
    const float* cqb = (const float*)d_in[5];
    const float* ckw = (const float*)d_in[6];
    const float* ckb = (const float*)d_in[7];
    const float* lrw = (const float*)d_in[8];
    const float* lrb = (const float*)d_in[9];
    const float* lti = (const float*)d_in[10];
    const float* tnw = (const float*)d_in[11];
    const float* tnb = (const float*)d_in[12];
    const float* W1i = (const float*)d_in[13];
    const float* b1i = (const float*)d_in[14];
    const float* pnw = (const float*)d_in[15];
    const float* pnb = (const float*)d_in[16];
    float* out = (float*)d_out;

    static int smem_set = 0;
    if (!smem_set) {
        cudaFuncSetAttribute(ttt_hgemm, cudaFuncAttributeMaxDynamicSharedMemorySize, 2 * GS_STAGE);
        smem_set = 1;
    }

    // fused QV+lr projection: A=hs, B=[q_w; v_w; lr_w; pad]
    ttt_cvtA<<<16384, 256>>>(hs);
    ttt_cvtB<<<NROWS_B, 256>>>(q_w, v_w, lrw);
    ttt_hgemm<<<dim3(33, 64), 256, 2 * GS_STAGE>>>(nullptr, 1);   // -> g_xq, g_xv, g_lrraw

    ttt_conv_rope<<<(ELEMS / 2) / 256, 256>>>(cqw, cqb, ckw, ckb);
    ttt_lr_sig<<<1024, 256>>>(lrb);
    ttt_scan_kernel<<<BZ * NHD, 256>>>(lti, tnw, tnb, W1i, b1i);

    // B for final GEMM (stream-ordered after GEMM1 read g_B_hf)
    ttt_cvtB<<<2048, 256>>>(o_w, o_w, o_w);
    ttt_postnorm_cvt<<<BZ * LZ, 256>>>(pnw, pnb);                 // -> g_A_hf

    ttt_hgemm<<<dim3(16, 64), 256, 2 * GS_STAGE>>>(out, 0);
}

// round 11
// speedup vs baseline: 1.1519x; 1.0518x over previous
#include <cuda_runtime.h>
#include <cuda_fp16.h>
#include <math.h>
#include <stdint.h>

#define BZ 4
#define LZ 2048
#define WD 2048
#define NHD 32
#define HDM 64
#define MBSZ 16
#define NMBC 128
#define EPSC 1e-6f
#define ELEMS (BZ*LZ*WD)
#define KP 4096            // split-fp16 A: [hi | lo]
#define NROWS_B 4224       // 2048 q + 2048 v + 32 lr + 96 pad (33*128)

// ---------------- scratch (device globals; no allocation) ----------------
__device__ float g_xq[ELEMS];
__device__ float g_xv[ELEMS];
__device__ float g_XQ[ELEMS];
__device__ float g_XK[ELEMS];
__device__ float g_scan[ELEMS];
__device__ float g_lr[BZ*NHD*NMBC*MBSZ];
__device__ float g_lrraw[8192 * 32];
__device__ __half g_A_hf[(size_t)8192 * KP];       // [hi | lo]
__device__ __half g_B_hf[(size_t)NROWS_B * 2048];  // hi plane only (dedup)

// ---------------- PTX helpers ----------------
__device__ __forceinline__ uint32_t smem_u32(const void* p) {
    uint32_t a;
    asm("{ .reg .u64 t; cvta.to.shared.u64 t, %1; cvt.u32.u64 %0, t; }" : "=r"(a) : "l"(p));
    return a;
}
#define CPA16(d, s) asm volatile("cp.async.cg.shared.global [%0], [%1], 16;" :: "r"(d), "l"(s) : "memory")
#define CPA_COMMIT() asm volatile("cp.async.commit_group;" ::: "memory")
#define CPA_WAIT0()  asm volatile("cp.async.wait_group 0;" ::: "memory")

__device__ __forceinline__ void ldsm_x4(uint32_t a, uint32_t& r0, uint32_t& r1, uint32_t& r2, uint32_t& r3) {
    asm volatile("ldmatrix.sync.aligned.m8n8.x4.shared.b16 {%0,%1,%2,%3}, [%4];"
                 : "=r"(r0), "=r"(r1), "=r"(r2), "=r"(r3) : "r"(a));
}
__device__ __forceinline__ void mma_f16(float* c, const uint32_t* a, const uint32_t* b) {
    asm volatile("mma.sync.aligned.m16n8k16.row.col.f32.f16.f16.f32 "
                 "{%0,%1,%2,%3}, {%4,%5,%6,%7}, {%8,%9}, {%0,%1,%2,%3};"
                 : "+f"(c[0]), "+f"(c[1]), "+f"(c[2]), "+f"(c[3])
                 : "r"(a[0]), "r"(a[1]), "r"(a[2]), "r"(a[3]), "r"(b[0]), "r"(b[1]));
}

// ---------------- split-fp16 helpers ----------------
__device__ __forceinline__ void splitf16(const float4& v, uint2& hi, uint2& lo) {
    __half2 h01 = __floats2half2_rn(v.x, v.y);
    __half2 h23 = __floats2half2_rn(v.z, v.w);
    float2 f01 = __half22float2(h01), f23 = __half22float2(h23);
    __half2 l01 = __floats2half2_rn(v.x - f01.x, v.y - f01.y);
    __half2 l23 = __floats2half2_rn(v.z - f23.x, v.w - f23.y);
    hi.x = *(uint32_t*)&h01; hi.y = *(uint32_t*)&h23;
    lo.x = *(uint32_t*)&l01; lo.y = *(uint32_t*)&l23;
}

// ---------------- A conversion: fp32 [8192,2048] -> fp16 [8192,4096] = [hi|lo] ----------------
__global__ __launch_bounds__(256) void ttt_cvtA(const float* __restrict__ src)
{
    int t = blockIdx.x * 256 + threadIdx.x;
    float4 v = ((const float4*)src)[t];
    int r = t >> 9, c4 = t & 511;
    size_t base = (size_t)r * KP + (c4 << 2);
    uint2 hi, lo;
    splitf16(v, hi, lo);
    *(uint2*)(g_A_hf + base)        = hi;
    *(uint2*)(g_A_hf + base + 2048) = lo;
}

// ---------------- B conversion (3 sources + zero pad): hi plane only ----------------
__global__ __launch_bounds__(256) void ttt_cvtB(const float* __restrict__ w0,
                                                const float* __restrict__ w1,
                                                const float* __restrict__ w2)
{
    int row = blockIdx.x;
    int tid = threadIdx.x;
    const float* srcp = nullptr;
    if (row < 2048) srcp = w0 + (size_t)row * 2048;
    else if (row < 4096) srcp = w1 + (size_t)(row - 2048) * 2048;
    else if (row < 4128) srcp = w2 + (size_t)(row - 4096) * 2048;
    float4 v0 = make_float4(0, 0, 0, 0), v1 = v0;
    if (srcp) { v0 = ((const float4*)srcp)[tid]; v1 = ((const float4*)srcp)[tid + 256]; }
    uint2 hi, lo;
    splitf16(v0, hi, lo);
    *(uint2*)(g_B_hf + (size_t)row * 2048 + (tid << 2)) = hi;
    splitf16(v1, hi, lo);
    *(uint2*)(g_B_hf + (size_t)row * 2048 + ((tid + 256) << 2)) = hi;
}

// ---------------- fp16 mma.sync GEMM: 128x128, 256 thr, B-dedup, 2-stage x 48KB ----------------
#define GS_STAGE 49152
#define GKSTEPS 32
__global__ __launch_bounds__(256, 2) void ttt_hgemm(float* Cext, int fused)
{
    extern __shared__ char smem[];
    uint32_t sb = smem_u32(smem);
    const int tid = threadIdx.x;
    const int wid = tid >> 5, lane = tid & 31;
    const int m0 = blockIdx.y << 7;
    const int n0 = blockIdx.x << 7;
    const int mw = (wid >> 2) << 6;
    const int nw = (wid & 3) << 5;

    const __half* Ab = g_A_hf + (size_t)m0 * KP;
    const __half* Bb = g_B_hf + (size_t)n0 * 2048;

    float acc[4][4][4];
#pragma unroll
    for (int i = 0; i < 4; i++)
#pragma unroll
        for (int j = 0; j < 4; j++)
#pragma unroll
            for (int q = 0; q < 4; q++) acc[i][j][q] = 0.0f;

    auto load_stage = [&](int s, int kt) {
        uint32_t sAh = sb + s * GS_STAGE;
        uint32_t sAl = sAh + 16384;
        uint32_t sB  = sAh + 32768;
#pragma unroll
        for (int i = 0; i < 4; i++) {
            int idx = tid + (i << 8);
            int row = idx >> 3, c = idx & 7;
            uint32_t soff = (uint32_t)(row << 7) + (((uint32_t)(c ^ (row & 7))) << 4);
            const __half* ar = Ab + (size_t)row * KP + kt * 64 + c * 8;
            CPA16(sAh + soff, (const char*)ar);
            CPA16(sAl + soff, (const char*)(ar + 2048));
            CPA16(sB + soff, (const char*)(Bb + (size_t)row * 2048 + kt * 64 + c * 8));
        }
        CPA_COMMIT();
    };

    load_stage(0, 0);
    const int lr15 = lane & 15, lhi = lane >> 4;

    for (int kt = 0; kt < GKSTEPS; kt++) {
        int s = kt & 1;
        if (kt + 1 < GKSTEPS) {
            load_stage(s ^ 1, kt + 1);
            asm volatile("cp.async.wait_group 1;" ::: "memory");
        } else {
            CPA_WAIT0();
        }
        __syncthreads();

        uint32_t aH = sb + s * GS_STAGE;
        uint32_t aL = aH + 16384;
        uint32_t bB = aH + 32768;
#pragma unroll
        for (int ks = 0; ks < 4; ks++) {
            uint32_t bf[4][2];
#pragma unroll
            for (int np = 0; np < 2; np++) {
                int row = nw + np * 16 + lr15;
                uint32_t bd = bB + (uint32_t)(row << 7) + ((uint32_t)((2 * ks + lhi) ^ (row & 7)) << 4);
                uint32_t r0, r1, r2, r3;
                ldsm_x4(bd, r0, r1, r2, r3);
                bf[np * 2][0] = r0;     bf[np * 2][1] = r2;
                bf[np * 2 + 1][0] = r1; bf[np * 2 + 1][1] = r3;
            }
            uint32_t af[4][4];
#pragma unroll
            for (int mt = 0; mt < 4; mt++) {
                int row = mw + mt * 16 + lr15;
                uint32_t ad = aH + (uint32_t)(row << 7) + ((uint32_t)((2 * ks + lhi) ^ (row & 7)) << 4);
                ldsm_x4(ad, af[mt][0], af[mt][1], af[mt][2], af[mt][3]);
            }
#pragma unroll
            for (int mt = 0; mt < 4; mt++)
#pragma unroll
                for (int nt = 0; nt < 4; nt++)
                    mma_f16(acc[mt][nt], af[mt], bf[nt]);
#pragma unroll
            for (int mt = 0; mt < 4; mt++) {
                int row = mw + mt * 16 + lr15;
                uint32_t ad = aL + (uint32_t)(row << 7) + ((uint32_t)((2 * ks + lhi) ^ (row & 7)) << 4);
                ldsm_x4(ad, af[mt][0], af[mt][1], af[mt][2], af[mt][3]);
            }
#pragma unroll
            for (int mt = 0; mt < 4; mt++)
#pragma unroll
                for (int nt = 0; nt < 4; nt++)
                    mma_f16(acc[mt][nt], af[mt], bf[nt]);
        }
        __syncthreads();
    }

#pragma unroll
    for (int mt = 0; mt < 4; mt++) {
#pragma unroll
        for (int nt = 0; nt < 4; nt++) {
            int col = n0 + nw + nt * 8 + (lane & 3) * 2;
            int row = m0 + mw + mt * 16 + (lane >> 2);
            float2 va = make_float2(acc[mt][nt][0], acc[mt][nt][1]);
            float2 vb = make_float2(acc[mt][nt][2], acc[mt][nt][3]);
            if (!fused) {
                *(float2*)(Cext + (size_t)row * 2048 + col) = va;
                *(float2*)(Cext + (size_t)(row + 8) * 2048 + col) = vb;
            } else if (col < 2048) {
                *(float2*)(g_xq + (size_t)row * 2048 + col) = va;
                *(float2*)(g_xq + (size_t)(row + 8) * 2048 + col) = vb;
            } else if (col < 4096) {
                *(float2*)(g_xv + (size_t)row * 2048 + col - 2048) = va;
                *(float2*)(g_xv + (size_t)(row + 8) * 2048 + col - 2048) = vb;
            } else if (col < 4128) {
                *(float2*)(g_lrraw + (size_t)row * 32 + col - 4096) = va;
                *(float2*)(g_lrraw + (size_t)(row + 8) * 32 + col - 4096) = vb;
            }
        }
    }
}

// ---------------- lr sigmoid + relayout ----------------
__global__ __launch_bounds__(256) void ttt_lr_sig(const float* __restrict__ lrb)
{
    int idx = blockIdx.x * 256 + threadIdx.x;
    int bl = idx >> 5, h = idx & 31;
    float v = g_lrraw[idx];
    float sg = 1.0f / (1.0f + expf(-(v + lrb[h])));
    int b = bl >> 11, l = bl & (LZ - 1);
    g_lr[(((size_t)b * NHD + h) * NMBC + (l >> 4)) * MBSZ + (l & 15)] = sg * (1.0f / 64.0f);
}

// ---------------- causal dwconv + RoPE (vectorized weights, uniform l) ----------------
__global__ __launch_bounds__(256) void ttt_conv_rope(
    const float* __restrict__ cqw, const float* __restrict__ cqb,
    const float* __restrict__ ckw, const float* __restrict__ ckb)
{
    __shared__ float scs[32], ssn[32];
    int idx = blockIdx.x * 256 + threadIdx.x;
    int pr = idx & (WD / 2 - 1);
    int bl = idx >> 10;
    int l  = bl & (LZ - 1);
    int ch = pr * 2;

    if (threadIdx.x < 32) {
        float fr = (float)(l & 15) * exp2f(-(float)threadIdx.x * (13.2877123795f / 32.0f));
        sincosf(fr, &ssn[threadIdx.x], &scs[threadIdx.x]);
    }
    __syncthreads();

    float4 wq0 = ((const float4*)cqw)[ch];
    float4 wq1 = ((const float4*)cqw)[ch + 1];
    float4 wk0 = ((const float4*)ckw)[ch];
    float4 wk1 = ((const float4*)ckw)[ch + 1];
    float2 bq = ((const float2*)cqb)[pr];
    float2 bk = ((const float2*)ckb)[pr];

    const float2* xin = (const float2*)g_xq;
    float q0 = bq.x, q1 = bq.y, k0 = bk.x, k1 = bk.y;
    if (l >= 3) {
        float2 v0 = xin[(size_t)(bl - 3) * (WD / 2) + pr];
        float2 v1 = xin[(size_t)(bl - 2) * (WD / 2) + pr];
        float2 v2 = xin[(size_t)(bl - 1) * (WD / 2) + pr];
        float2 v3 = xin[(size_t)bl * (WD / 2) + pr];
        q0 += v0.x * wq0.x + v1.x * wq0.y + v2.x * wq0.z + v3.x * wq0.w;
        q1 += v0.y * wq1.x + v1.y * wq1.y + v2.y * wq1.z + v3.y * wq1.w;
        k0 += v0.x * wk0.x + v1.x * wk0.y + v2.x * wk0.z + v3.x * wk0.w;
        k1 += v0.y * wk1.x + v1.y * wk1.y + v2.y * wk1.z + v3.y * wk1.w;
    } else {
        const float* wq0a = (const float*)&wq0;
        const float* wq1a = (const float*)&wq1;
        const float* wk0a = (const float*)&wk0;
        const float* wk1a = (const float*)&wk1;
#pragma unroll
        for (int k = 0; k < 4; k++) {
            if (l - 3 + k >= 0) {
                float2 v = xin[(size_t)(bl - 3 + k) * (WD / 2) + pr];
                q0 += v.x * wq0a[k];  q1 += v.y * wq1a[k];
                k0 += v.x * wk0a[k];  k1 += v.y * wk1a[k];
            }
        }
    }
    int i = (ch & 63) >> 1;
    float sn = ssn[i], cs = scs[i];
    ((float2*)g_XQ)[idx] = make_float2(q0 * cs - q1 * sn, q1 * cs + q0 * sn);
    ((float2*)g_XK)[idx] = make_float2(k0 * cs - k1 * sn, k1 * cs + k0 * sn);
}

// ---------------- TTT scan: one block (256 thr) per (b,h), cp.async double-buffer ----------------
__global__ __launch_bounds__(256) void ttt_scan_kernel(
    const float* __restrict__ lt_idx,
    const float* __restrict__ lnw_g, const float* __restrict__ lnb_g,
    const float* __restrict__ W1g,   const float* __restrict__ b1g)
{
    __shared__ float W1[64][64];
    __shared__ float sxq[2][16][68], sxk[2][16][68], sxv[2][16][68];
    __shared__ float lrbuf[2][16];
    __shared__ float grad[16][68], z[16][68];
    __shared__ float attn[16][16];
    __shared__ float b1[64], lnw[64], lnb[64], tok[16];

    int tid = threadIdx.x;
    int b = blockIdx.x >> 5, h = blockIdx.x & 31;

    for (int o = tid; o < 4096; o += 256)
        ((float*)W1)[o] = W1g[(size_t)h * 4096 + o];
    if (tid < 64) {
        b1[tid]  = b1g[h * 64 + tid];
        lnw[tid] = lnw_g[h * 64 + tid];
        lnb[tid] = lnb_g[h * 64 + tid];
    }
    if (tid < 16) tok[tid] = fmaxf(1.0f / (float)(tid + 1) + lt_idx[tid], 0.0f);

    const int warp = tid >> 5, lane = tid & 31;
    const int ii = tid >> 4;
    const int d0 = (tid & 15) * 4;
    const size_t base = ((size_t)b * LZ) * WD + (size_t)h * HDM;
    const size_t lrbase = (((size_t)b * NHD + h) * NMBC) * MBSZ;

    // smem addresses for cp.async
    const uint32_t a_xq = smem_u32(&sxq[0][0][0]);
    const uint32_t a_xk = smem_u32(&sxk[0][0][0]);
    const uint32_t a_xv = smem_u32(&sxv[0][0][0]);
    const uint32_t a_lr = smem_u32(&lrbuf[0][0]);
    const uint32_t BUFB = 16 * 68 * 4;        // bytes per buffer
    const uint32_t rowoff = (uint32_t)(ii * 68 * 4 + d0 * 4);

    auto prefetch = [&](int s, int n) {
        size_t g0 = base + (size_t)(n * MBSZ + ii) * WD + d0;
        uint32_t so = s * BUFB + rowoff;
        CPA16(a_xq + so, (const char*)&g_XQ[g0]);
        CPA16(a_xk + so, (const char*)&g_XK[g0]);
        CPA16(a_xv + so, (const char*)&g_xv[g0]);
        if (tid < 4)
            CPA16(a_lr + s * 64 + tid * 16, (const char*)&g_lr[lrbase + n * MBSZ + tid * 4]);
        CPA_COMMIT();
    };

    prefetch(0, 0);

    for (int n = 0; n < NMBC; n++) {
        const int s = n & 1;
        CPA_WAIT0();
        __syncthreads();
        if (n + 1 < NMBC) prefetch(s ^ 1, n + 1);

        const float* lr = lrbuf[s];

        // Z1 = xk @ W1 + b1
        {
            float4 acc = *(const float4*)&b1[d0];
#pragma unroll 8
            for (int e = 0; e < 64; e++) {
                float xe = sxk[s][ii][e];
                float4 w = *(const float4*)&W1[e][d0];
                acc.x += xe * w.x; acc.y += xe * w.y; acc.z += xe * w.z; acc.w += xe * w.w;
            }
            *(float4*)&z[ii][d0] = acc;
        }
        // attn
        {
            int i = tid >> 4, j = tid & 15;
            float sa = 0.0f;
#pragma unroll 8
            for (int d = 0; d < 64; d++) sa += sxq[s][i][d] * sxk[s][j][d];
            attn[i][j] = sa;
        }
        __syncthreads();

        // grad = ln_l2_bwd(Z1, xv-xk)
        {
#pragma unroll
            for (int rr = 0; rr < 2; rr++) {
                int r = warp * 2 + rr;
                float x0 = z[r][lane], x1 = z[r][lane + 32];
                float sm = x0 + x1;
#pragma unroll
                for (int o = 16; o; o >>= 1) sm += __shfl_xor_sync(0xffffffffu, sm, o);
                float mu = sm * (1.0f / 64.0f);
                float e0 = x0 - mu, e1 = x1 - mu;
                float v = e0 * e0 + e1 * e1;
#pragma unroll
                for (int o = 16; o; o >>= 1) v += __shfl_xor_sync(0xffffffffu, v, o);
                float rstd = rsqrtf(v * (1.0f / 64.0f) + EPSC);
                float xh0 = e0 * rstd, xh1 = e1 * rstd;
                float t0 = sxv[s][r][lane] - sxk[s][r][lane];
                float t1 = sxv[s][r][lane + 32] - sxk[s][r][lane + 32];
                float gy0 = (lnw[lane] * xh0 + lnb[lane] - t0) * lnw[lane];
                float gy1 = (lnw[lane + 32] * xh1 + lnb[lane + 32] - t1) * lnw[lane + 32];
                float s1 = gy0 + gy1, s2 = gy0 * xh0 + gy1 * xh1;
#pragma unroll
                for (int o = 16; o; o >>= 1) {
                    s1 += __shfl_xor_sync(0xffffffffu, s1, o);
                    s2 += __shfl_xor_sync(0xffffffffu, s2, o);
                }
                float sc = rstd * (1.0f / 64.0f);
                grad[r][lane]      = (64.0f * gy0 - s1 - xh0 * s2) * sc;
                grad[r][lane + 32] = (64.0f * gy1 - s1 - xh1 * s2) * sc;
            }
        }
        __syncthreads();

        // Z1_bar
        {
            float4 acc = *(const float4*)&b1[d0];
#pragma unroll 8
            for (int e = 0; e < 64; e++) {
                float xe = sxq[s][ii][e];
                float4 w = *(const float4*)&W1[e][d0];
                acc.x += xe * w.x; acc.y += xe * w.y; acc.z += xe * w.z; acc.w += xe * w.w;
            }
            float tk = tok[ii];
            for (int j = 0; j <= ii; j++) {
                float cf = tk * lr[j] * (attn[ii][j] + 1.0f);
                float4 gr = *(const float4*)&grad[j][d0];
                acc.x -= cf * gr.x; acc.y -= cf * gr.y; acc.z -= cf * gr.z; acc.w -= cf * gr.w;
            }
            *(float4*)&z[ii][d0] = acc;
        }
        __syncthreads();

        // out = xq + ln_fwd(Z1_bar)
        {
#pragma unroll
            for (int rr = 0; rr < 2; rr++) {
                int r = warp * 2 + rr;
                float x0 = z[r][lane], x1 = z[r][lane + 32];
                float sm = x0 + x1;
#pragma unroll
                for (int o = 16; o; o >>= 1) sm += __shfl_xor_sync(0xffffffffu, sm, o);
                float mu = sm * (1.0f / 64.0f);
                float e0 = x0 - mu, e1 = x1 - mu;
                float v = e0 * e0 + e1 * e1;
#pragma unroll
                for (int o = 16; o; o >>= 1) v += __shfl_xor_sync(0xffffffffu, v, o);
                float rstd = rsqrtf(v * (1.0f / 64.0f) + EPSC);
                size_t go = base + (size_t)(n * MBSZ + r) * WD;
                g_scan[go + lane]      = sxq[s][r][lane]      + lnw[lane] * (e0 * rstd)      + lnb[lane];
                g_scan[go + lane + 32] = sxq[s][r][lane + 32] + lnw[lane + 32] * (e1 * rstd) + lnb[lane + 32];
            }
        }

        // W1/b1 state update
        {
            float te = tok[15];
#pragma unroll
            for (int p = 0; p < 4; p++) {
                int d = ii * 4 + p;
                float4 acc = *(const float4*)&W1[d][d0];
#pragma unroll
                for (int j = 0; j < 16; j++) {
                    float cf = te * lr[j] * sxk[s][j][d];
                    float4 gr = *(const float4*)&grad[j][d0];
                    acc.x -= cf * gr.x; acc.y -= cf * gr.y; acc.z -= cf * gr.z; acc.w -= cf * gr.w;
                }
                *(float4*)&W1[d][d0] = acc;
            }
            if (tid < 64) {
                float sm = 0.0f;
#pragma unroll
                for (int j = 0; j < 16; j++) sm += lr[j] * grad[j][tid];
                b1[tid] -= te * sm;
            }
        }
        __syncthreads();
    }
}

// ---------------- post layer-norm fused with A split-fp16 conversion ----------------
__global__ __launch_bounds__(256) void ttt_postnorm_cvt(
    const float* __restrict__ pw, const float* __restrict__ pb)
{
    __shared__ float red[8];
    int bl = blockIdx.x, tid = threadIdx.x;
    int lane = tid & 31, warp = tid >> 5;
    const float4* src = (const float4*)(g_scan + (size_t)bl * WD);
    float4 v0 = src[tid], v1 = src[tid + 256];

    float s = v0.x + v0.y + v0.z + v0.w + v1.x + v1.y + v1.z + v1.w;
#pragma unroll
    for (int o = 16; o; o >>= 1) s += __shfl_xor_sync(0xffffffffu, s, o);
    if (lane == 0) red[warp] = s;
    __syncthreads();
    float tot = 0.0f;
#pragma unroll
    for (int i = 0; i < 8; i++) tot += red[i];
    float mu = tot * (1.0f / 2048.0f);
    __syncthreads();

    float q =
        (v0.x - mu) * (v0.x - mu) + (v0.y - mu) * (v0.y - mu) +
        (v0.z - mu) * (v0.z - mu) + (v0.w - mu) * (v0.w - mu) +
        (v1.x - mu) * (v1.x - mu) + (v1.y - mu) * (v1.y - mu) +
        (v1.z - mu) * (v1.z - mu) + (v1.w - mu) * (v1.w - mu);
#pragma unroll
    for (int o = 16; o; o >>= 1) q += __shfl_xor_sync(0xffffffffu, q, o);
    if (lane == 0) red[warp] = q;
    __syncthreads();
    float qt = 0.0f;
#pragma unroll
    for (int i = 0; i < 8; i++) qt += red[i];
    float rstd = rsqrtf(qt * (1.0f / 2048.0f) + EPSC);

    float4 w0 = ((const float4*)pw)[tid], w1 = ((const float4*)pw)[tid + 256];
    float4 b0 = ((const float4*)pb)[tid], b1v = ((const float4*)pb)[tid + 256];
    float4 o0, o1;
    o0.x = (v0.x - mu) * rstd * w0.x + b0.x;
    o0.y = (v0.y - mu) * rstd * w0.y + b0.y;
    o0.z = (v0.z - mu) * rstd * w0.z + b0.z;
    o0.w = (v0.w - mu) * rstd * w0.w + b0.w;
    o1.x = (v1.x - mu) * rstd * w1.x + b1v.x;
    o1.y = (v1.y - mu) * rstd * w1.y + b1v.y;
    o1.z = (v1.z - mu) * rstd * w1.z + b1v.z;
    o1.w = (v1.w - mu) * rstd * w1.w + b1v.w;

    size_t base0 = (size_t)bl * KP + (tid << 2);
    size_t base1 = (size_t)bl * KP + ((tid + 256) << 2);
    uint2 hi, lo;
    splitf16(o0, hi, lo);
    *(uint2*)(g_A_hf + base0)        = hi;
    *(uint2*)(g_A_hf + base0 + 2048) = lo;
    splitf16(o1, hi, lo);
    *(uint2*)(g_A_hf + base1)        = hi;
    *(uint2*)(g_A_hf + base1 + 2048) = lo;
}

// ---------------- launcher ----------------
extern "C" void kernel_launch(void* const* d_in, const int* in_sizes, int n_in,
                              void* d_out, int out_size)
{
    const float* hs  = (const float*)d_in[0];
    const float* q_w = (const float*)d_in[1];
    const float* v_w = (const float*)d_in[2];
    const float* o_w = (const float*)d_in[3];
    const float* cqw = (const float*)d_in[4];
    const float* cqb = (const float*)d_in[5];
    const float* ckw = (const float*)d_in[6];
    const float* ckb = (const float*)d_in[7];
    const float* lrw = (const float*)d_in[8];
    const float* lrb = (const float*)d_in[9];
    const float* lti = (const float*)d_in[10];
    const float* tnw = (const float*)d_in[11];
    const float* tnb = (const float*)d_in[12];
    const float* W1i = (const float*)d_in[13];
    const float* b1i = (const float*)d_in[14];
    const float* pnw = (const float*)d_in[15];
    const float* pnb = (const float*)d_in[16];
    float* out = (float*)d_out;

    static int smem_set = 0;
    if (!smem_set) {
        cudaFuncSetAttribute(ttt_hgemm, cudaFuncAttributeMaxDynamicSharedMemorySize, 2 * GS_STAGE);
        smem_set = 1;
    }

    // fused QV+lr projection: A=hs, B=[q_w; v_w; lr_w; pad]
    ttt_cvtA<<<16384, 256>>>(hs);
    ttt_cvtB<<<NROWS_B, 256>>>(q_w, v_w, lrw);
    ttt_hgemm<<<dim3(33, 64), 256, 2 * GS_STAGE>>>(nullptr, 1);   // -> g_xq, g_xv, g_lrraw

    ttt_conv_rope<<<(ELEMS / 2) / 256, 256>>>(cqw, cqb, ckw, ckb);
    ttt_lr_sig<<<1024, 256>>>(lrb);
    ttt_scan_kernel<<<BZ * NHD, 256>>>(lti, tnw, tnb, W1i, b1i);

    // B for final GEMM (stream-ordered after GEMM1 read g_B_hf)
    ttt_cvtB<<<2048, 256>>>(o_w, o_w, o_w);
    ttt_postnorm_cvt<<<BZ * LZ, 256>>>(pnw, pnb);                 // -> g_A_hf

    ttt_hgemm<<<dim3(16, 64), 256, 2 * GS_STAGE>>>(out, 0);
}